// round 5
// baseline (speedup 1.0000x reference)
#include <cuda_runtime.h>
#include <math.h>

#define NN   50000
#define EE   800000
#define E2   (EE + NN)
#define DD   128
#define HH   8
#define CC   16
#define HID  64
#define OUTC 40

// ---------------- scratch (device globals; 256B-aligned for vector/red.v4 access) ----------------
__device__ __align__(256) int    g_rows[EE];
__device__ __align__(256) int    g_cols[EE];
__device__ __align__(256) float  g_xproj[NN * DD];
__device__ __align__(256) float  g_h[NN * DD];      // GAT linear output; later classifier hidden (N x 64)
__device__ __align__(256) float  g_agg[NN * DD];    // GAT aggregation; later h_sparse
__device__ __align__(256) float  g_act[NN * DD];    // h1
__device__ __align__(256) float  g_hbase[NN * DD];  // h_base
__device__ __align__(256) float  g_prc[NN * DD];    // [pr | pc]
__device__ __align__(256) float  g_asrc[NN * HH];
__device__ __align__(256) float  g_adst[NN * HH];
__device__ __align__(256) float  g_m[NN * HH];
__device__ __align__(256) float  g_den[NN * HH];
__device__ __align__(256) double g_s1[DD];
__device__ __align__(256) double g_s2[DD];
__device__ __align__(256) float  g_scale[DD];
__device__ __align__(256) float  g_shift[DD];
__device__ __align__(256) float  g_wcomb[DD * DD];
__device__ __align__(256) float  g_logits[NN * OUTC];
__device__ int g_is64;

// ---------------- helpers ----------------
__device__ __forceinline__ void atomicMaxFloat(float* addr, float val) {
    if (val >= 0.f) atomicMax((int*)addr, __float_as_int(val));
    else            atomicMin((unsigned int*)addr, __float_as_uint(val));
}

__device__ __forceinline__ void atomicAddF4(float4* addr, float4 v) {
    asm volatile("red.global.add.v4.f32 [%0], {%1, %2, %3, %4};"
                 :: "l"(addr), "f"(v.x), "f"(v.y), "f"(v.z), "f"(v.w) : "memory");
}

// ---------------- edge-index dtype detection ----------------
// If the harness delivered int64 (little-endian) values < 2^31, every odd
// 32-bit word of the first 128 values is 0. With real int32 edge data those
// words are further edge indices (random in [0, 50000)) -> ~surely nonzero.
__global__ void detect_dtype_kernel(const int* __restrict__ ei32) {
    if (threadIdx.x == 0) {
        int odd_nonzero = 0;
        for (int i = 0; i < 128; i++) odd_nonzero |= (ei32[2 * i + 1] != 0);
        g_is64 = odd_nonzero ? 0 : 1;
    }
}

__global__ void prep_edges_kernel(const void* __restrict__ ei,
                                  int* __restrict__ rows, int* __restrict__ cols) {
    int i = blockIdx.x * blockDim.x + threadIdx.x;
    if (i >= EE) return;
    int r, c;
    if (g_is64) {
        const long long* p = (const long long*)ei;
        r = (int)p[i]; c = (int)p[EE + i];
    } else {
        const int* p = (const int*)ei;
        r = p[i]; c = p[EE + i];
    }
    // clamp: turns any surprise into wrong-answer (measurable) not a crash
    r = min(max(r, 0), NN - 1);
    c = min(max(c, 0), NN - 1);
    rows[i] = r; cols[i] = c;
}

__global__ void pack_wcomb_kernel(const float* __restrict__ Ws1, float* __restrict__ wc) {
    int i = blockIdx.x * blockDim.x + threadIdx.x;
    if (i >= DD * DD) return;
    int j = i >> 7, k = i & 127;
    wc[i] = (j < 64) ? Ws1[j * 256 + k] : Ws1[(j - 64) * 256 + 128 + k];
}

// ---------------- GEMM: out[n, m] = sum_k A[n,k]*W[m,k] (+bias) ; K = 128 ----------------
__global__ __launch_bounds__(256) void gemm_nt_kernel(
    const float* __restrict__ A, const float* __restrict__ W,
    const float* __restrict__ bias, float* __restrict__ out, int n, int mout)
{
    __shared__ float sA[64][65];
    __shared__ float sW[64][65];
    int rb = blockIdx.x * 64;
    int cb = blockIdx.y * 64;
    int tid = threadIdx.x;
    int tr = tid >> 4, tc = tid & 15;
    float acc[4][4];
#pragma unroll
    for (int i = 0; i < 4; i++)
#pragma unroll
        for (int j = 0; j < 4; j++) acc[i][j] = 0.f;

    for (int k0 = 0; k0 < DD; k0 += 64) {
#pragma unroll
        for (int p = 0; p < 4; p++) {
            int i = tid + p * 256;      // float4 id 0..1023
            int r = i >> 4;
            int kc = (i & 15) << 2;
            int gr = rb + r;
            float4 v = make_float4(0.f, 0.f, 0.f, 0.f);
            if (gr < n) v = *(const float4*)(A + (size_t)gr * DD + k0 + kc);
            sA[r][kc] = v.x; sA[r][kc + 1] = v.y; sA[r][kc + 2] = v.z; sA[r][kc + 3] = v.w;
            int gc = cb + r;
            float4 w = make_float4(0.f, 0.f, 0.f, 0.f);
            if (gc < mout) w = *(const float4*)(W + (size_t)gc * DD + k0 + kc);
            sW[r][kc] = w.x; sW[r][kc + 1] = w.y; sW[r][kc + 2] = w.z; sW[r][kc + 3] = w.w;
        }
        __syncthreads();
#pragma unroll 16
        for (int k = 0; k < 64; k++) {
            float a0 = sA[tr * 4 + 0][k], a1 = sA[tr * 4 + 1][k];
            float a2 = sA[tr * 4 + 2][k], a3 = sA[tr * 4 + 3][k];
            float w0 = sW[tc * 4 + 0][k], w1 = sW[tc * 4 + 1][k];
            float w2 = sW[tc * 4 + 2][k], w3 = sW[tc * 4 + 3][k];
            acc[0][0] += a0 * w0; acc[0][1] += a0 * w1; acc[0][2] += a0 * w2; acc[0][3] += a0 * w3;
            acc[1][0] += a1 * w0; acc[1][1] += a1 * w1; acc[1][2] += a1 * w2; acc[1][3] += a1 * w3;
            acc[2][0] += a2 * w0; acc[2][1] += a2 * w1; acc[2][2] += a2 * w2; acc[2][3] += a2 * w3;
            acc[3][0] += a3 * w0; acc[3][1] += a3 * w1; acc[3][2] += a3 * w2; acc[3][3] += a3 * w3;
        }
        __syncthreads();
    }
#pragma unroll
    for (int i = 0; i < 4; i++) {
        int r = rb + tr * 4 + i;
        if (r >= n) continue;
#pragma unroll
        for (int j = 0; j < 4; j++) {
            int c = cb + tc * 4 + j;
            if (c < mout) out[(size_t)r * mout + c] = acc[i][j] + (bias ? bias[c] : 0.f);
        }
    }
}

// ---------------- attention coefficients ----------------
__global__ void attn_kernel(const float* __restrict__ h, const float* __restrict__ as,
                            const float* __restrict__ ad,
                            float* __restrict__ asrc, float* __restrict__ adst) {
    int idx = blockIdx.x * blockDim.x + threadIdx.x;
    int node = idx >> 7;
    int j = idx & 127;
    if (node >= NN) return;
    float v = h[(size_t)node * DD + j];
    float s = v * as[j];
    float d = v * ad[j];
#pragma unroll
    for (int off = 8; off >= 1; off >>= 1) {
        s += __shfl_down_sync(0xffffffffu, s, off, 16);
        d += __shfl_down_sync(0xffffffffu, d, off, 16);
    }
    if ((j & 15) == 0) {
        asrc[node * HH + (j >> 4)] = s;
        adst[node * HH + (j >> 4)] = d;
    }
}

// ---------------- per-layer init ----------------
__global__ void gat_init_kernel(float* __restrict__ agg, float* __restrict__ m,
                                float* __restrict__ den, double* __restrict__ s1,
                                double* __restrict__ s2) {
    int stride = gridDim.x * blockDim.x;
    for (int i = blockIdx.x * blockDim.x + threadIdx.x; i < NN * DD; i += stride) {
        agg[i] = 0.f;
        if (i < NN * HH) { m[i] = -1e30f; den[i] = 0.f; }
        if (i < DD) { s1[i] = 0.0; s2[i] = 0.0; }
    }
}

__global__ void zero_stats_kernel(double* s1, double* s2) {
    int j = threadIdx.x;
    if (j < DD) { s1[j] = 0.0; s2[j] = 0.0; }
}

// ---------------- edge pass 1: segment max ----------------
__global__ void edge_max_kernel(const int* __restrict__ rows, const int* __restrict__ cols,
                                const float* __restrict__ asrc, const float* __restrict__ adst,
                                float* __restrict__ m) {
    int e = blockIdx.x * blockDim.x + threadIdx.x;
    if (e >= E2) return;
    int s, d;
    if (e < EE) { s = rows[e]; d = cols[e]; } else { s = e - EE; d = s; }
    float4 s0 = *(const float4*)(asrc + s * HH);
    float4 s1 = *(const float4*)(asrc + s * HH + 4);
    float4 d0 = *(const float4*)(adst + d * HH);
    float4 d1 = *(const float4*)(adst + d * HH + 4);
    float ev[8] = { s0.x + d0.x, s0.y + d0.y, s0.z + d0.z, s0.w + d0.w,
                    s1.x + d1.x, s1.y + d1.y, s1.z + d1.z, s1.w + d1.w };
    float* mp = m + (size_t)d * HH;
#pragma unroll
    for (int hh = 0; hh < 8; hh++) {
        float v = ev[hh]; v = v > 0.f ? v : 0.2f * v;
        atomicMaxFloat(mp + hh, v);
    }
}

// ---------------- edge pass 2: segment sum of exp ----------------
__global__ void edge_den_kernel(const int* __restrict__ rows, const int* __restrict__ cols,
                                const float* __restrict__ asrc, const float* __restrict__ adst,
                                const float* __restrict__ m, float* __restrict__ den) {
    int e = blockIdx.x * blockDim.x + threadIdx.x;
    if (e >= E2) return;
    int s, d;
    if (e < EE) { s = rows[e]; d = cols[e]; } else { s = e - EE; d = s; }
    float4 s0 = *(const float4*)(asrc + s * HH);
    float4 s1 = *(const float4*)(asrc + s * HH + 4);
    float4 d0 = *(const float4*)(adst + d * HH);
    float4 d1 = *(const float4*)(adst + d * HH + 4);
    float4 m0 = *(const float4*)(m + (size_t)d * HH);
    float4 m1 = *(const float4*)(m + (size_t)d * HH + 4);
    float ev[8] = { s0.x + d0.x, s0.y + d0.y, s0.z + d0.z, s0.w + d0.w,
                    s1.x + d1.x, s1.y + d1.y, s1.z + d1.z, s1.w + d1.w };
    float mm[8] = { m0.x, m0.y, m0.z, m0.w, m1.x, m1.y, m1.z, m1.w };
    float p[8];
#pragma unroll
    for (int hh = 0; hh < 8; hh++) {
        float v = ev[hh]; v = v > 0.f ? v : 0.2f * v;
        p[hh] = __expf(v - mm[hh]);
    }
    atomicAddF4((float4*)(den + (size_t)d * HH),     make_float4(p[0], p[1], p[2], p[3]));
    atomicAddF4((float4*)(den + (size_t)d * HH) + 1, make_float4(p[4], p[5], p[6], p[7]));
}

// ---------------- edge pass 3: weighted message scatter (warp per edge) ----------------
__global__ void edge_msg_kernel(const int* __restrict__ rows, const int* __restrict__ cols,
                                const float* __restrict__ asrc, const float* __restrict__ adst,
                                const float* __restrict__ m, const float* __restrict__ den,
                                const float* __restrict__ hlin, float* __restrict__ agg) {
    int gt = blockIdx.x * blockDim.x + threadIdx.x;
    int e = gt >> 5, lane = gt & 31;
    if (e >= E2) return;
    int s, d;
    if (e < EE) { s = rows[e]; d = cols[e]; } else { s = e - EE; d = s; }
    int hh = lane >> 2;
    float ev = asrc[s * HH + hh] + adst[d * HH + hh];
    ev = ev > 0.f ? ev : 0.2f * ev;
    float alpha = __expf(ev - m[(size_t)d * HH + hh]) / (den[(size_t)d * HH + hh] + 1e-16f);
    float4 v = *((const float4*)(hlin + (size_t)s * DD) + lane);
    v.x *= alpha; v.y *= alpha; v.z *= alpha; v.w *= alpha;
    atomicAddF4((float4*)(agg + (size_t)d * DD) + lane, v);
}

// ---------------- batchnorm ----------------
__global__ void bn_stats_kernel(const float* __restrict__ x, double* __restrict__ s1,
                                double* __restrict__ s2, int dc) {
    int j = threadIdx.x & (dc - 1);
    int rpb = 256 / dc;
    int r = blockIdx.x * rpb + threadIdx.x / dc;
    int stride = gridDim.x * rpb;
    double ds = 0.0, dq = 0.0;
    for (; r < NN; r += stride) {
        float v = x[(size_t)r * dc + j];
        ds += v; dq += (double)v * v;
    }
    atomicAdd(&s1[j], ds);
    atomicAdd(&s2[j], dq);
}

__global__ void bn_final_kernel(const double* __restrict__ s1, const double* __restrict__ s2,
                                const float* __restrict__ g, const float* __restrict__ be,
                                float* __restrict__ scale, float* __restrict__ shift, int dc) {
    int j = threadIdx.x;
    if (j >= dc) return;
    double mu = s1[j] / (double)NN;
    double var = s2[j] / (double)NN - mu * mu;
    float sc = (float)((double)g[j] * rsqrt(var + 1e-5));
    scale[j] = sc;
    shift[j] = be[j] - (float)mu * sc;
}

// mode 0 = ELU, 1 = ReLU
__global__ void bn_apply_kernel(const float* __restrict__ x, const float* __restrict__ scale,
                                const float* __restrict__ shift, float* __restrict__ out,
                                float* __restrict__ out2, int total, int dc, int mode) {
    int i = blockIdx.x * blockDim.x + threadIdx.x;
    if (i >= total) return;
    int j = i & (dc - 1);
    float v = fmaf(x[i], scale[j], shift[j]);
    v = mode ? fmaxf(v, 0.f) : (v > 0.f ? v : expm1f(v));
    out[i] = v;
    if (out2) out2[i] = v;
}

// ---------------- edge scorer + gumbel hard sample (warp per edge) ----------------
__global__ void edge_logits_kernel(const int* __restrict__ rows, const int* __restrict__ cols,
                                   const float* __restrict__ prc, const float* __restrict__ bs1,
                                   const float* __restrict__ Ws2, const float* __restrict__ bs2,
                                   const float* __restrict__ gumbel,
                                   float* __restrict__ wts, float* __restrict__ lraw) {
    int gt = blockIdx.x * blockDim.x + threadIdx.x;
    int e = gt >> 5, lane = gt & 31;
    if (e >= EE) return;
    int r = rows[e], c = cols[e];
    const float* pr = prc + (size_t)r * DD;
    const float* pc = prc + (size_t)c * DD + 64;
    float v0 = pr[lane] + pc[lane] + bs1[lane];
    float v1 = pr[lane + 32] + pc[lane + 32] + bs1[lane + 32];
    float acc = fmaxf(v0, 0.f) * Ws2[lane] + fmaxf(v1, 0.f) * Ws2[lane + 32];
#pragma unroll
    for (int off = 16; off >= 1; off >>= 1) acc += __shfl_xor_sync(0xffffffffu, acc, off);
    if (lane == 0) {
        float L = acc + bs2[0];
        lraw[e] = L;
        // straight-through gumbel: weights = argmax([g0, L+g1]) == 1
        wts[e] = (L + gumbel[2 * e + 1] > gumbel[2 * e]) ? 1.f : 0.f;
    }
}

// ---------------- sparse aggregation (warp per edge, weights in {0,1}) ----------------
__global__ void edge_agg_kernel(const int* __restrict__ rows, const int* __restrict__ cols,
                                const float* __restrict__ wts, const float* __restrict__ hbase,
                                float* __restrict__ hsp) {
    int gt = blockIdx.x * blockDim.x + threadIdx.x;
    int e = gt >> 5, lane = gt & 31;
    if (e >= EE) return;
    if (wts[e] == 0.f) return;
    int r = rows[e], c = cols[e];
    float4 v = *((const float4*)(hbase + (size_t)c * DD) + lane);
    atomicAddF4((float4*)(hsp + (size_t)r * DD) + lane, v);
}

// ---------------- classifier head ----------------
__global__ void cls_kernel(const float* __restrict__ cact, const float* __restrict__ Wc2,
                           const float* __restrict__ bc2, float* __restrict__ logits) {
    int i = blockIdx.x * blockDim.x + threadIdx.x;
    if (i >= NN * OUTC) return;
    int n = i / OUTC, o = i - n * OUTC;
    const float4* cr = (const float4*)(cact + (size_t)n * HID);
    const float4* wr = (const float4*)(Wc2 + o * HID);
    float acc = bc2[o];
#pragma unroll
    for (int k = 0; k < 16; k++) {
        float4 a = cr[k], w = wr[k];
        acc += a.x * w.x + a.y * w.y + a.z * w.z + a.w * w.w;
    }
    logits[i] = acc;
}

__global__ void logsm_kernel(const float* __restrict__ logits, float* __restrict__ out) {
    int gt = blockIdx.x * blockDim.x + threadIdx.x;
    int n = gt >> 5, lane = gt & 31;
    if (n >= NN) return;
    const float* p = logits + (size_t)n * OUTC;
    float a = p[lane];
    float b = (lane < 8) ? p[32 + lane] : -3.4e38f;
    float mx = fmaxf(a, b);
#pragma unroll
    for (int off = 16; off >= 1; off >>= 1) mx = fmaxf(mx, __shfl_xor_sync(0xffffffffu, mx, off));
    float se = __expf(a - mx) + ((lane < 8) ? __expf(b - mx) : 0.f);
#pragma unroll
    for (int off = 16; off >= 1; off >>= 1) se += __shfl_xor_sync(0xffffffffu, se, off);
    float lse = mx + logf(se);
    out[(size_t)n * OUTC + lane] = a - lse;
    if (lane < 8) out[(size_t)n * OUTC + 32 + lane] = b - lse;
}

// ---------------- host launch ----------------
extern "C" void kernel_launch(void* const* d_in, const int* in_sizes, int n_in,
                              void* d_out, int out_size) {
    (void)in_sizes; (void)n_in; (void)out_size;
    const float*     x      = (const float*)d_in[0];
    const void*      ei     = d_in[1];
    const float*     gumbel = (const float*)d_in[2];
    const float*     W_res  = (const float*)d_in[3];
    const float*     b_res  = (const float*)d_in[4];
    const float*     Wg1    = (const float*)d_in[5];
    const float*     as1    = (const float*)d_in[6];
    const float*     ad1    = (const float*)d_in[7];
    const float*     gam1   = (const float*)d_in[9];
    const float*     bet1   = (const float*)d_in[10];
    const float*     Wg2    = (const float*)d_in[11];
    const float*     as2    = (const float*)d_in[12];
    const float*     ad2    = (const float*)d_in[13];
    const float*     gam2   = (const float*)d_in[15];
    const float*     bet2   = (const float*)d_in[16];
    const float*     Ws1    = (const float*)d_in[17];
    const float*     bs1    = (const float*)d_in[18];
    const float*     Ws2    = (const float*)d_in[19];
    const float*     bs2    = (const float*)d_in[20];
    const float*     Wc1    = (const float*)d_in[21];
    const float*     gc     = (const float*)d_in[23];
    const float*     bec    = (const float*)d_in[24];
    const float*     Wc2    = (const float*)d_in[25];
    const float*     bc2    = (const float*)d_in[26];

    float* out      = (float*)d_out;
    float* out_logp = out;
    float* out_w    = out + (size_t)NN * OUTC;
    float* out_lr   = out_w + EE;

    int *rows, *cols;
    float *xproj, *h, *agg, *act, *hbase, *prc, *asrc, *adst, *m, *den;
    float *scale, *shift, *wcomb, *logits;
    double *s1, *s2;
    cudaGetSymbolAddress((void**)&rows, g_rows);
    cudaGetSymbolAddress((void**)&cols, g_cols);
    cudaGetSymbolAddress((void**)&xproj, g_xproj);
    cudaGetSymbolAddress((void**)&h, g_h);
    cudaGetSymbolAddress((void**)&agg, g_agg);
    cudaGetSymbolAddress((void**)&act, g_act);
    cudaGetSymbolAddress((void**)&hbase, g_hbase);
    cudaGetSymbolAddress((void**)&prc, g_prc);
    cudaGetSymbolAddress((void**)&asrc, g_asrc);
    cudaGetSymbolAddress((void**)&adst, g_adst);
    cudaGetSymbolAddress((void**)&m, g_m);
    cudaGetSymbolAddress((void**)&den, g_den);
    cudaGetSymbolAddress((void**)&s1, g_s1);
    cudaGetSymbolAddress((void**)&s2, g_s2);
    cudaGetSymbolAddress((void**)&scale, g_scale);
    cudaGetSymbolAddress((void**)&shift, g_shift);
    cudaGetSymbolAddress((void**)&wcomb, g_wcomb);
    cudaGetSymbolAddress((void**)&logits, g_logits);

    const int ROWB = (NN + 63) / 64;           // 782
    dim3 g128(ROWB, 2), g64(ROWB, 1);
    const int EB  = (E2 + 255) / 256;          // 3321
    const int MB  = (E2 * 32) / 256;           // 106250
    const int LB  = (EE * 32) / 256;           // 100000

    // prep
    detect_dtype_kernel<<<1, 32>>>((const int*)ei);
    prep_edges_kernel<<<(EE + 255) / 256, 256>>>(ei, rows, cols);
    pack_wcomb_kernel<<<(DD * DD + 255) / 256, 256>>>(Ws1, wcomb);

    // x_proj
    gemm_nt_kernel<<<g128, 256>>>(x, W_res, b_res, xproj, NN, DD);

    // ---- GAT layer 1 ----
    gemm_nt_kernel<<<g128, 256>>>(xproj, Wg1, nullptr, h, NN, DD);
    attn_kernel<<<(NN * DD) / 256, 256>>>(h, as1, ad1, asrc, adst);
    gat_init_kernel<<<4096, 256>>>(agg, m, den, s1, s2);
    edge_max_kernel<<<EB, 256>>>(rows, cols, asrc, adst, m);
    edge_den_kernel<<<EB, 256>>>(rows, cols, asrc, adst, m, den);
    edge_msg_kernel<<<MB, 256>>>(rows, cols, asrc, adst, m, den, h, agg);
    bn_stats_kernel<<<512, 256>>>(agg, s1, s2, DD);
    bn_final_kernel<<<1, DD>>>(s1, s2, gam1, bet1, scale, shift, DD);
    bn_apply_kernel<<<(NN * DD + 255) / 256, 256>>>(agg, scale, shift, act, nullptr, NN * DD, DD, 0);

    // ---- GAT layer 2 ----
    gemm_nt_kernel<<<g128, 256>>>(act, Wg2, nullptr, h, NN, DD);
    attn_kernel<<<(NN * DD) / 256, 256>>>(h, as2, ad2, asrc, adst);
    gat_init_kernel<<<4096, 256>>>(agg, m, den, s1, s2);
    edge_max_kernel<<<EB, 256>>>(rows, cols, asrc, adst, m);
    edge_den_kernel<<<EB, 256>>>(rows, cols, asrc, adst, m, den);
    edge_msg_kernel<<<MB, 256>>>(rows, cols, asrc, adst, m, den, h, agg);
    bn_stats_kernel<<<512, 256>>>(agg, s1, s2, DD);
    bn_final_kernel<<<1, DD>>>(s1, s2, gam2, bet2, scale, shift, DD);
    // write h_base and also seed h_sparse accumulator (in-place dual write)
    bn_apply_kernel<<<(NN * DD + 255) / 256, 256>>>(agg, scale, shift, hbase, agg, NN * DD, DD, 0);

    // ---- edge scorer + sparse agg ----
    gemm_nt_kernel<<<g128, 256>>>(hbase, wcomb, nullptr, prc, NN, DD);
    edge_logits_kernel<<<LB, 256>>>(rows, cols, prc, bs1, Ws2, bs2, gumbel, out_w, out_lr);
    edge_agg_kernel<<<LB, 256>>>(rows, cols, out_w, hbase, agg);

    // ---- classifier ----
    gemm_nt_kernel<<<g64, 256>>>(agg, Wc1, nullptr, h, NN, HID);  // h := N x 64
    zero_stats_kernel<<<1, DD>>>(s1, s2);
    bn_stats_kernel<<<512, 256>>>(h, s1, s2, HID);
    bn_final_kernel<<<1, HID>>>(s1, s2, gc, bec, scale, shift, HID);
    bn_apply_kernel<<<(NN * HID + 255) / 256, 256>>>(h, scale, shift, h, nullptr, NN * HID, HID, 1);
    cls_kernel<<<(NN * OUTC + 255) / 256, 256>>>(h, Wc2, bc2, logits);
    logsm_kernel<<<(NN * 32) / 256, 256>>>(logits, out_logp);
}

// round 7
// speedup vs baseline: 1.1678x; 1.1678x over previous
#include <cuda_runtime.h>
#include <math.h>

#define NN   50000
#define EE   800000
#define E2   (EE + NN)
#define DD   128
#define HH   8
#define HID  64
#define OUTC 40

// ---------------- scratch ----------------
__device__ __align__(256) int    g_rows[EE];
__device__ __align__(256) int    g_cols[EE];
__device__ __align__(256) float  g_xproj[NN * DD];
__device__ __align__(256) float  g_h[NN * DD];
__device__ __align__(256) float  g_agg[NN * DD];
__device__ __align__(256) float  g_act[NN * DD];
__device__ __align__(256) float  g_hbase[NN * DD];
__device__ __align__(256) float  g_prc[NN * DD];
__device__ __align__(256) float  g_asrc[NN * HH];
__device__ __align__(256) float  g_adst[NN * HH];
__device__ __align__(256) float  g_den[NN * HH];
__device__ __align__(256) double g_s1[DD];
__device__ __align__(256) double g_s2[DD];
__device__ __align__(256) float  g_scale[DD];
__device__ __align__(256) float  g_shift[DD];
__device__ __align__(256) float  g_wcomb[DD * DD];
__device__ __align__(256) float  g_logits[NN * OUTC];
__device__ int g_is64;

__device__ __forceinline__ void atomicAddF4(float4* addr, float4 v) {
    asm volatile("red.global.add.v4.f32 [%0], {%1, %2, %3, %4};"
                 :: "l"(addr), "f"(v.x), "f"(v.y), "f"(v.z), "f"(v.w) : "memory");
}

// ---------------- edge-index dtype detection ----------------
__global__ void detect_dtype_kernel(const int* __restrict__ ei32) {
    if (threadIdx.x == 0) {
        int odd_nonzero = 0;
        for (int i = 0; i < 128; i++) odd_nonzero |= (ei32[2 * i + 1] != 0);
        g_is64 = odd_nonzero ? 0 : 1;
    }
}

__global__ void prep_edges_kernel(const void* __restrict__ ei,
                                  int* __restrict__ rows, int* __restrict__ cols) {
    int i = blockIdx.x * blockDim.x + threadIdx.x;
    if (i >= EE) return;
    int r, c;
    if (g_is64) {
        const long long* p = (const long long*)ei;
        r = (int)p[i]; c = (int)p[EE + i];
    } else {
        const int* p = (const int*)ei;
        r = p[i]; c = p[EE + i];
    }
    r = min(max(r, 0), NN - 1);
    c = min(max(c, 0), NN - 1);
    rows[i] = r; cols[i] = c;
}

__global__ void pack_wcomb_kernel(const float* __restrict__ Ws1, float* __restrict__ wc) {
    int i = blockIdx.x * blockDim.x + threadIdx.x;
    if (i >= DD * DD) return;
    int j = i >> 7, k = i & 127;
    wc[i] = (j < 64) ? Ws1[j * 256 + k] : Ws1[(j - 64) * 256 + 128 + k];
}

// ---------------- GEMM: out[n,m] = sum_k A[n,k]*W[m,k] (+bias); K=128 ----------------
// Transposed k-major smem tiles (pad 68 keeps LDS.128 16B-aligned):
// inner loop = 2x LDS.128 + 16 FFMA -> FMA-bound instead of smem-wavefront-bound.
__global__ __launch_bounds__(256) void gemm_nt_kernel(
    const float* __restrict__ A, const float* __restrict__ W,
    const float* __restrict__ bias, float* __restrict__ out, int n, int mout)
{
    __shared__ float sAT[64][68];   // [k][row]
    __shared__ float sWT[64][68];   // [k][col]
    int rb = blockIdx.x * 64;
    int cb = blockIdx.y * 64;
    int tid = threadIdx.x;
    int tr = tid >> 4, tc = tid & 15;
    float acc[4][4];
#pragma unroll
    for (int i = 0; i < 4; i++)
#pragma unroll
        for (int j = 0; j < 4; j++) acc[i][j] = 0.f;

    for (int k0 = 0; k0 < DD; k0 += 64) {
#pragma unroll
        for (int p = 0; p < 4; p++) {
            int li = tid + p * 256;        // 0..1023
            int r  = li >> 4;              // 0..63
            int kc = (li & 15) << 2;       // 0..60
            int gr = rb + r;
            float4 v = make_float4(0.f, 0.f, 0.f, 0.f);
            if (gr < n) v = *(const float4*)(A + (size_t)gr * DD + k0 + kc);
            sAT[kc + 0][r] = v.x; sAT[kc + 1][r] = v.y;
            sAT[kc + 2][r] = v.z; sAT[kc + 3][r] = v.w;
            int gc = cb + r;
            float4 w = make_float4(0.f, 0.f, 0.f, 0.f);
            if (gc < mout) w = *(const float4*)(W + (size_t)gc * DD + k0 + kc);
            sWT[kc + 0][r] = w.x; sWT[kc + 1][r] = w.y;
            sWT[kc + 2][r] = w.z; sWT[kc + 3][r] = w.w;
        }
        __syncthreads();
#pragma unroll 8
        for (int k = 0; k < 64; k++) {
            float4 a = *(const float4*)&sAT[k][tr * 4];
            float4 w = *(const float4*)&sWT[k][tc * 4];
            acc[0][0] += a.x * w.x; acc[0][1] += a.x * w.y; acc[0][2] += a.x * w.z; acc[0][3] += a.x * w.w;
            acc[1][0] += a.y * w.x; acc[1][1] += a.y * w.y; acc[1][2] += a.y * w.z; acc[1][3] += a.y * w.w;
            acc[2][0] += a.z * w.x; acc[2][1] += a.z * w.y; acc[2][2] += a.z * w.z; acc[2][3] += a.z * w.w;
            acc[3][0] += a.w * w.x; acc[3][1] += a.w * w.y; acc[3][2] += a.w * w.z; acc[3][3] += a.w * w.w;
        }
        __syncthreads();
    }
    int c0 = cb + tc * 4;
    float4 bv = make_float4(0.f, 0.f, 0.f, 0.f);
    if (bias) bv = *(const float4*)(bias + c0);
#pragma unroll
    for (int i = 0; i < 4; i++) {
        int r = rb + tr * 4 + i;
        if (r >= n) continue;
        float4 o = make_float4(acc[i][0] + bv.x, acc[i][1] + bv.y,
                               acc[i][2] + bv.z, acc[i][3] + bv.w);
        *(float4*)(out + (size_t)r * mout + c0) = o;
    }
}

// ---------------- attention coefficients ----------------
__global__ void attn_kernel(const float* __restrict__ h, const float* __restrict__ as,
                            const float* __restrict__ ad,
                            float* __restrict__ asrc, float* __restrict__ adst) {
    int idx = blockIdx.x * blockDim.x + threadIdx.x;
    int node = idx >> 7;
    int j = idx & 127;
    if (node >= NN) return;
    float v = h[(size_t)node * DD + j];
    float s = v * as[j];
    float d = v * ad[j];
#pragma unroll
    for (int off = 8; off >= 1; off >>= 1) {
        s += __shfl_down_sync(0xffffffffu, s, off, 16);
        d += __shfl_down_sync(0xffffffffu, d, off, 16);
    }
    if ((j & 15) == 0) {
        asrc[node * HH + (j >> 4)] = s;
        adst[node * HH + (j >> 4)] = d;
    }
}

// ---------------- edge pass 1: segment sum of exp (no max shift; |e| is O(10)) ----------------
__global__ void edge_den_kernel(const int* __restrict__ rows, const int* __restrict__ cols,
                                const float* __restrict__ asrc, const float* __restrict__ adst,
                                float* __restrict__ den) {
    int e = blockIdx.x * blockDim.x + threadIdx.x;
    if (e >= E2) return;
    int s, d;
    if (e < EE) { s = rows[e]; d = cols[e]; } else { s = e - EE; d = s; }
    float4 s0 = *(const float4*)(asrc + s * HH);
    float4 s1 = *(const float4*)(asrc + s * HH + 4);
    float4 d0 = *(const float4*)(adst + d * HH);
    float4 d1 = *(const float4*)(adst + d * HH + 4);
    float ev[8] = { s0.x + d0.x, s0.y + d0.y, s0.z + d0.z, s0.w + d0.w,
                    s1.x + d1.x, s1.y + d1.y, s1.z + d1.z, s1.w + d1.w };
    float p[8];
#pragma unroll
    for (int hh = 0; hh < 8; hh++) {
        float v = ev[hh]; v = v > 0.f ? v : 0.2f * v;
        p[hh] = __expf(v);
    }
    atomicAddF4((float4*)(den + (size_t)d * HH),     make_float4(p[0], p[1], p[2], p[3]));
    atomicAddF4((float4*)(den + (size_t)d * HH) + 1, make_float4(p[4], p[5], p[6], p[7]));
}

// ---------------- edge pass 2: weighted message scatter (warp per edge) ----------------
__global__ void edge_msg_kernel(const int* __restrict__ rows, const int* __restrict__ cols,
                                const float* __restrict__ asrc, const float* __restrict__ adst,
                                const float* __restrict__ den,
                                const float* __restrict__ hlin, float* __restrict__ agg) {
    int gt = blockIdx.x * blockDim.x + threadIdx.x;
    int e = gt >> 5, lane = gt & 31;
    if (e >= E2) return;
    int s, d;
    if (e < EE) { s = rows[e]; d = cols[e]; } else { s = e - EE; d = s; }
    int hh = lane >> 2;
    float ev = asrc[s * HH + hh] + adst[d * HH + hh];
    ev = ev > 0.f ? ev : 0.2f * ev;
    float alpha = __expf(ev) / (den[(size_t)d * HH + hh] + 1e-16f);
    float4 v = *((const float4*)(hlin + (size_t)s * DD) + lane);
    v.x *= alpha; v.y *= alpha; v.z *= alpha; v.w *= alpha;
    atomicAddF4((float4*)(agg + (size_t)d * DD) + lane, v);
}

// ---------------- batchnorm ----------------
__global__ void bn_stats_kernel(const float* __restrict__ x, double* __restrict__ s1,
                                double* __restrict__ s2, int dc) {
    int j = threadIdx.x & (dc - 1);
    int rpb = 256 / dc;
    int r = blockIdx.x * rpb + threadIdx.x / dc;
    int stride = gridDim.x * rpb;
    double ds = 0.0, dq = 0.0;
    for (; r < NN; r += stride) {
        float v = x[(size_t)r * dc + j];
        ds += v; dq += (double)v * v;
    }
    atomicAdd(&s1[j], ds);
    atomicAdd(&s2[j], dq);
}

__global__ void bn_final_kernel(const double* __restrict__ s1, const double* __restrict__ s2,
                                const float* __restrict__ g, const float* __restrict__ be,
                                float* __restrict__ scale, float* __restrict__ shift, int dc) {
    int j = threadIdx.x;
    if (j >= dc) return;
    double mu = s1[j] / (double)NN;
    double var = s2[j] / (double)NN - mu * mu;
    float sc = (float)((double)g[j] * rsqrt(var + 1e-5));
    scale[j] = sc;
    shift[j] = be[j] - (float)mu * sc;
}

// mode 0 = ELU, 1 = ReLU
__global__ void bn_apply_kernel(const float* __restrict__ x, const float* __restrict__ scale,
                                const float* __restrict__ shift, float* __restrict__ out,
                                float* __restrict__ out2, int total, int dc, int mode) {
    int i = blockIdx.x * blockDim.x + threadIdx.x;
    if (i >= total) return;
    int j = i & (dc - 1);
    float v = fmaf(x[i], scale[j], shift[j]);
    v = mode ? fmaxf(v, 0.f) : (v > 0.f ? v : expm1f(v));
    out[i] = v;
    if (out2) out2[i] = v;
}

// ---------------- fused edge scorer + gumbel sample + sparse agg (warp per edge) ----------------
__global__ void edge_score_agg_kernel(const int* __restrict__ rows, const int* __restrict__ cols,
                                      const float* __restrict__ prc, const float* __restrict__ bs1,
                                      const float* __restrict__ Ws2, const float* __restrict__ bs2,
                                      const float* __restrict__ gumbel,
                                      const float* __restrict__ hbase, float* __restrict__ hsp,
                                      float* __restrict__ wts, float* __restrict__ lraw) {
    int gt = blockIdx.x * blockDim.x + threadIdx.x;
    int e = gt >> 5, lane = gt & 31;
    if (e >= EE) return;
    int r = rows[e], c = cols[e];
    const float* pr = prc + (size_t)r * DD;
    const float* pc = prc + (size_t)c * DD + 64;
    float v0 = pr[lane] + pc[lane] + bs1[lane];
    float v1 = pr[lane + 32] + pc[lane + 32] + bs1[lane + 32];
    float acc = fmaxf(v0, 0.f) * Ws2[lane] + fmaxf(v1, 0.f) * Ws2[lane + 32];
#pragma unroll
    for (int off = 16; off >= 1; off >>= 1) acc += __shfl_xor_sync(0xffffffffu, acc, off);
    float L = acc + bs2[0];
    float w = (L + gumbel[2 * e + 1] > gumbel[2 * e]) ? 1.f : 0.f;
    if (lane == 0) { lraw[e] = L; wts[e] = w; }
    if (w != 0.f) {
        float4 v = *((const float4*)(hbase + (size_t)c * DD) + lane);
        atomicAddF4((float4*)(hsp + (size_t)r * DD) + lane, v);
    }
}

// ---------------- classifier head ----------------
__global__ void cls_kernel(const float* __restrict__ cact, const float* __restrict__ Wc2,
                           const float* __restrict__ bc2, float* __restrict__ logits) {
    int i = blockIdx.x * blockDim.x + threadIdx.x;
    if (i >= NN * OUTC) return;
    int n = i / OUTC, o = i - n * OUTC;
    const float4* cr = (const float4*)(cact + (size_t)n * HID);
    const float4* wr = (const float4*)(Wc2 + o * HID);
    float acc = bc2[o];
#pragma unroll
    for (int k = 0; k < 16; k++) {
        float4 a = cr[k], w = wr[k];
        acc += a.x * w.x + a.y * w.y + a.z * w.z + a.w * w.w;
    }
    logits[i] = acc;
}

__global__ void logsm_kernel(const float* __restrict__ logits, float* __restrict__ out) {
    int gt = blockIdx.x * blockDim.x + threadIdx.x;
    int n = gt >> 5, lane = gt & 31;
    if (n >= NN) return;
    const float* p = logits + (size_t)n * OUTC;
    float a = p[lane];
    float b = (lane < 8) ? p[32 + lane] : -3.4e38f;
    float mx = fmaxf(a, b);
#pragma unroll
    for (int off = 16; off >= 1; off >>= 1) mx = fmaxf(mx, __shfl_xor_sync(0xffffffffu, mx, off));
    float se = __expf(a - mx) + ((lane < 8) ? __expf(b - mx) : 0.f);
#pragma unroll
    for (int off = 16; off >= 1; off >>= 1) se += __shfl_xor_sync(0xffffffffu, se, off);
    float lse = mx + logf(se);
    out[(size_t)n * OUTC + lane] = a - lse;
    if (lane < 8) out[(size_t)n * OUTC + 32 + lane] = b - lse;
}

// ---------------- host launch ----------------
extern "C" void kernel_launch(void* const* d_in, const int* in_sizes, int n_in,
                              void* d_out, int out_size) {
    (void)in_sizes; (void)n_in; (void)out_size;
    const float* x      = (const float*)d_in[0];
    const void*  ei     = d_in[1];
    const float* gumbel = (const float*)d_in[2];
    const float* W_res  = (const float*)d_in[3];
    const float* b_res  = (const float*)d_in[4];
    const float* Wg1    = (const float*)d_in[5];
    const float* as1    = (const float*)d_in[6];
    const float* ad1    = (const float*)d_in[7];
    const float* gam1   = (const float*)d_in[9];
    const float* bet1   = (const float*)d_in[10];
    const float* Wg2    = (const float*)d_in[11];
    const float* as2    = (const float*)d_in[12];
    const float* ad2    = (const float*)d_in[13];
    const float* gam2   = (const float*)d_in[15];
    const float* bet2   = (const float*)d_in[16];
    const float* Ws1    = (const float*)d_in[17];
    const float* bs1    = (const float*)d_in[18];
    const float* Ws2    = (const float*)d_in[19];
    const float* bs2    = (const float*)d_in[20];
    const float* Wc1    = (const float*)d_in[21];
    const float* gc     = (const float*)d_in[23];
    const float* bec    = (const float*)d_in[24];
    const float* Wc2    = (const float*)d_in[25];
    const float* bc2    = (const float*)d_in[26];

    float* out      = (float*)d_out;
    float* out_logp = out;
    float* out_w    = out + (size_t)NN * OUTC;
    float* out_lr   = out_w + EE;

    int *rows, *cols;
    float *xproj, *h, *agg, *act, *hbase, *prc, *asrc, *adst, *den;
    float *scale, *shift, *wcomb, *logits;
    double *s1, *s2;
    cudaGetSymbolAddress((void**)&rows, g_rows);
    cudaGetSymbolAddress((void**)&cols, g_cols);
    cudaGetSymbolAddress((void**)&xproj, g_xproj);
    cudaGetSymbolAddress((void**)&h, g_h);
    cudaGetSymbolAddress((void**)&agg, g_agg);
    cudaGetSymbolAddress((void**)&act, g_act);
    cudaGetSymbolAddress((void**)&hbase, g_hbase);
    cudaGetSymbolAddress((void**)&prc, g_prc);
    cudaGetSymbolAddress((void**)&asrc, g_asrc);
    cudaGetSymbolAddress((void**)&adst, g_adst);
    cudaGetSymbolAddress((void**)&den, g_den);
    cudaGetSymbolAddress((void**)&s1, g_s1);
    cudaGetSymbolAddress((void**)&s2, g_s2);
    cudaGetSymbolAddress((void**)&scale, g_scale);
    cudaGetSymbolAddress((void**)&shift, g_shift);
    cudaGetSymbolAddress((void**)&wcomb, g_wcomb);
    cudaGetSymbolAddress((void**)&logits, g_logits);

    const int ROWB = (NN + 63) / 64;           // 782
    dim3 g128(ROWB, 2), g64(ROWB, 1);
    const int EB = (E2 + 255) / 256;
    const int MB = (E2 * 32 + 255) / 256;
    const int LB = (EE * 32) / 256;

    // prep
    detect_dtype_kernel<<<1, 32>>>((const int*)ei);
    prep_edges_kernel<<<(EE + 255) / 256, 256>>>(ei, rows, cols);
    pack_wcomb_kernel<<<(DD * DD + 255) / 256, 256>>>(Ws1, wcomb);

    // x_proj
    gemm_nt_kernel<<<g128, 256>>>(x, W_res, b_res, xproj, NN, DD);

    // ---- GAT layer 1 ----
    gemm_nt_kernel<<<g128, 256>>>(xproj, Wg1, nullptr, h, NN, DD);
    attn_kernel<<<(NN * DD) / 256, 256>>>(h, as1, ad1, asrc, adst);
    cudaMemsetAsync(agg, 0, (size_t)NN * DD * sizeof(float));
    cudaMemsetAsync(den, 0, (size_t)NN * HH * sizeof(float));
    cudaMemsetAsync(s1, 0, DD * sizeof(double));
    cudaMemsetAsync(s2, 0, DD * sizeof(double));
    edge_den_kernel<<<EB, 256>>>(rows, cols, asrc, adst, den);
    edge_msg_kernel<<<MB, 256>>>(rows, cols, asrc, adst, den, h, agg);
    bn_stats_kernel<<<512, 256>>>(agg, s1, s2, DD);
    bn_final_kernel<<<1, DD>>>(s1, s2, gam1, bet1, scale, shift, DD);
    bn_apply_kernel<<<(NN * DD + 255) / 256, 256>>>(agg, scale, shift, act, nullptr, NN * DD, DD, 0);

    // ---- GAT layer 2 ----
    gemm_nt_kernel<<<g128, 256>>>(act, Wg2, nullptr, h, NN, DD);
    attn_kernel<<<(NN * DD) / 256, 256>>>(h, as2, ad2, asrc, adst);
    cudaMemsetAsync(agg, 0, (size_t)NN * DD * sizeof(float));
    cudaMemsetAsync(den, 0, (size_t)NN * HH * sizeof(float));
    cudaMemsetAsync(s1, 0, DD * sizeof(double));
    cudaMemsetAsync(s2, 0, DD * sizeof(double));
    edge_den_kernel<<<EB, 256>>>(rows, cols, asrc, adst, den);
    edge_msg_kernel<<<MB, 256>>>(rows, cols, asrc, adst, den, h, agg);
    bn_stats_kernel<<<512, 256>>>(agg, s1, s2, DD);
    bn_final_kernel<<<1, DD>>>(s1, s2, gam2, bet2, scale, shift, DD);
    // write h_base and seed h_sparse accumulator
    bn_apply_kernel<<<(NN * DD + 255) / 256, 256>>>(agg, scale, shift, hbase, agg, NN * DD, DD, 0);

    // ---- edge scorer + sparse agg (fused) ----
    gemm_nt_kernel<<<g128, 256>>>(hbase, wcomb, nullptr, prc, NN, DD);
    edge_score_agg_kernel<<<LB, 256>>>(rows, cols, prc, bs1, Ws2, bs2, gumbel,
                                       hbase, agg, out_w, out_lr);

    // ---- classifier ----
    gemm_nt_kernel<<<g64, 256>>>(agg, Wc1, nullptr, h, NN, HID);
    cudaMemsetAsync(s1, 0, DD * sizeof(double));
    cudaMemsetAsync(s2, 0, DD * sizeof(double));
    bn_stats_kernel<<<512, 256>>>(h, s1, s2, HID);
    bn_final_kernel<<<1, HID>>>(s1, s2, gc, bec, scale, shift, HID);
    bn_apply_kernel<<<(NN * HID + 255) / 256, 256>>>(h, scale, shift, h, nullptr, NN * HID, HID, 1);
    cls_kernel<<<(NN * OUTC + 255) / 256, 256>>>(h, Wc2, bc2, logits);
    logsm_kernel<<<(NN * 32) / 256, 256>>>(logits, out_logp);
}